// round 2
// baseline (speedup 1.0000x reference)
#include <cuda_runtime.h>
#include <math.h>

typedef unsigned long long ull;
#define NCTA 128
#define TPB  256

// ---- device scratch (static; allocations are forbidden) ----
__device__ float g_u[512u*1024u*64u];   // u[t][d][b]
__device__ float g_x[2][64*1024];       // state ping-pong, layout [b][k]
__device__ int   g_len[64];
__device__ unsigned g_bar_count;
__device__ unsigned g_bar_gen;

// ---- packed f32x2 helpers ----
__device__ __forceinline__ ull pack2(float a, float b){ ull r; asm("mov.b64 %0,{%1,%2};":"=l"(r):"f"(a),"f"(b)); return r; }
__device__ __forceinline__ float2 unpk(ull v){ float2 r; asm("mov.b64 {%0,%1},%2;":"=f"(r.x),"=f"(r.y):"l"(v)); return r; }
__device__ __forceinline__ ull ffma2(ull a, ull b, ull c){ ull d; asm("fma.rn.f32x2 %0,%1,%2,%3;":"=l"(d):"l"(a),"l"(b),"l"(c)); return d; }

// ---- init: broadcast x0 into g_x[0] ([b][k]), zero lengths ----
__global__ void init_kernel(const float* __restrict__ x0) {
    int idx = blockIdx.x * 256 + threadIdx.x;           // 65536 threads
    g_x[0][idx] = x0[idx & 1023];
    if (idx < 64) g_len[idx] = 0;
}

// ---- lengths: count timesteps whose feature-sum != 0 ----
__global__ void len_kernel(const float* __restrict__ emb) {
    int t = blockIdx.x;                                  // 512 blocks
    int b = threadIdx.x >> 2, p = threadIdx.x & 3;
    const float* row = emb + ((size_t)t*64 + b)*300;
    float s = 0.f;
    for (int i = p; i < 300; i += 4) s += row[i];
    s += __shfl_xor_sync(0xffffffffu, s, 1);
    s += __shfl_xor_sync(0xffffffffu, s, 2);
    if (p == 0 && s != 0.f) atomicAdd(&g_len[b], 1);
}

// ---- projection: u[t][d][b] = sum_k win[d][k]*emb[t][b][k] + bias[d] ----
__global__ __launch_bounds__(256) void proj_kernel(const float* __restrict__ emb,
                                                   const float* __restrict__ win,
                                                   const float* __restrict__ bias) {
    __align__(16) __shared__ float Es[32][66];   // [kk][b], padded
    __align__(16) __shared__ float Ws[32][64];   // [kk][d_local]
    const int tid = threadIdx.x;
    const int tx = tid & 15;          // b-group: b = tx*4..+3
    const int ty = tid >> 4;          // d-group: d = ty*4..+3
    const int t  = blockIdx.y;
    const int d0 = blockIdx.x * 64;
    const int lb = tid >> 2, lq = tid & 3;

    ull acc[4][2];
    #pragma unroll
    for (int i = 0; i < 4; ++i) { acc[i][0] = 0ull; acc[i][1] = 0ull; }

    for (int k0 = 0; k0 < 300; k0 += 32) {
        #pragma unroll
        for (int j = 0; j < 8; ++j) {
            int kk = lq*8 + j, k = k0 + kk;
            Es[kk][lb] = (k < 300) ? emb[((size_t)t*64 + lb)*300 + k] : 0.f;
            Ws[kk][lb] = (k < 300) ? win[((size_t)(d0 + lb))*300 + k] : 0.f;
        }
        __syncthreads();
        #pragma unroll
        for (int kk = 0; kk < 32; ++kk) {
            ull e01 = *(const ull*)&Es[kk][tx*4];
            ull e23 = *(const ull*)&Es[kk][tx*4 + 2];
            #pragma unroll
            for (int dd = 0; dd < 4; ++dd) {
                float w = Ws[kk][ty*4 + dd];
                ull wp = pack2(w, w);
                acc[dd][0] = ffma2(e01, wp, acc[dd][0]);
                acc[dd][1] = ffma2(e23, wp, acc[dd][1]);
            }
        }
        __syncthreads();
    }
    #pragma unroll
    for (int dd = 0; dd < 4; ++dd) {
        int d = d0 + ty*4 + dd;
        float bb = bias[d];
        float2 p0 = unpk(acc[dd][0]), p1 = unpk(acc[dd][1]);
        float4 o = make_float4(p0.x + bb, p0.y + bb, p1.x + bb, p1.y + bb);
        *(float4*)&g_u[((size_t)t*1024 + d)*64 + tx*4] = o;
    }
}

// ---- grid-wide barrier (all NCTA CTAs resident: grid <= SM count) ----
__device__ __forceinline__ void grid_barrier() {
    __syncthreads();
    if (threadIdx.x == 0) {
        __threadfence();
        volatile unsigned* genp = &g_bar_gen;
        unsigned gen = *genp;
        if (atomicAdd(&g_bar_count, 1u) == NCTA - 1u) {
            atomicExch(&g_bar_count, 0u);
            __threadfence();
            *genp = gen + 1u;
        } else {
            while (*genp == gen) { }
            __threadfence();
        }
    }
    __syncthreads();
}

// ---- persistent scan: x' = mask * (0.5*tanh(u + x W^T) + 0.5*x) ----
__global__ __launch_bounds__(TPB, 1) void scan_kernel(const float* __restrict__ layer_w,
                                                      const float* __restrict__ init_state,
                                                      float* __restrict__ out) {
    // W pairs: wsm viewed as ull wpair[rg][k] = (W[base+2rg][k], W[base+2rg+1][k])
    __align__(16) __shared__ float wsm[8 * 1024];     // 32 KB
    __align__(16) __shared__ float4 xs4[1024];        // 16 KB: 64 b x 16 groups, swizzled

    const int tid = threadIdx.x;
    const int b   = tid & 63;
    const int rg  = tid >> 6;           // 0..3
    const int base = blockIdx.x * 8;
    const int d0 = base + rg * 2;

    for (int r = 0; r < 8; ++r) {
        const float* wr = layer_w + (size_t)(base + r) * 1024;
        for (int k = tid; k < 1024; k += TPB)
            wsm[(r >> 1) * 2048 + k * 2 + (r & 1)] = wr[k];
    }
    float xo0 = init_state[d0], xo1 = init_state[d0 + 1];
    const int len_b = g_len[b];
    const ull* wrow0 = (const ull*)wsm + rg * 1024;

    for (int t = 0; t < 512; ++t) {
        const float* xin = g_x[t & 1];
        float* xout = g_x[(t & 1) ^ 1];
        size_t ub = (((size_t)t * 1024) + d0) * 64 + b;
        ull acc = pack2(g_u[ub], g_u[ub + 64]);

        for (int c = 0; c < 16; ++c) {
            __syncthreads();
            #pragma unroll
            for (int jj = 0; jj < 4; ++jj) {
                int f = jj * 256 + tid;              // 0..1023
                int bb = f >> 4, g = f & 15;
                float4 v = __ldcg((const float4*)(xin + (size_t)bb * 1024 + c * 64) + g);
                xs4[bb * 16 + (g ^ (bb & 15))] = v;
            }
            __syncthreads();
            const ull* wrow = wrow0 + c * 64;
            #pragma unroll
            for (int g = 0; g < 16; ++g) {
                float4 xv = xs4[b * 16 + (g ^ (b & 15))];
                ulonglong2 wa = *(const ulonglong2*)(wrow + g * 4);
                ulonglong2 wb = *(const ulonglong2*)(wrow + g * 4 + 2);
                acc = ffma2(pack2(xv.x, xv.x), wa.x, acc);
                acc = ffma2(pack2(xv.y, xv.y), wa.y, acc);
                acc = ffma2(pack2(xv.z, xv.z), wb.x, acc);
                acc = ffma2(pack2(xv.w, xv.w), wb.y, acc);
            }
        }
        float2 a = unpk(acc);
        float n0 = 0.5f * tanhf(a.x) + 0.5f * xo0;
        float n1 = 0.5f * tanhf(a.y) + 0.5f * xo1;
        if (t >= len_b) { n0 = 0.f; n1 = 0.f; }
        xo0 = n0; xo1 = n1;
        *(float2*)(xout + (size_t)b * 1024 + d0) = make_float2(n0, n1);
        *(float2*)(out + ((size_t)b * 512 + t) * 1024 + d0) = make_float2(n0, n1);
        grid_barrier();
    }
}

__global__ void tail_kernel(float* out) {
    int b = threadIdx.x;
    if (b < 64) out[33554432u + b] = (float)g_len[b];
}

extern "C" void kernel_launch(void* const* d_in, const int* in_sizes, int n_in,
                              void* d_out, int out_size) {
    const float* emb  = (const float*)d_in[0];
    const float* win  = (const float*)d_in[1];
    const float* lw   = (const float*)d_in[2];
    const float* bias = (const float*)d_in[3];
    const float* x0   = (const float*)d_in[4];
    float* out = (float*)d_out;

    init_kernel<<<256, 256>>>(x0);
    len_kernel<<<512, 256>>>(emb);
    proj_kernel<<<dim3(16, 512), 256>>>(emb, win, bias);
    scan_kernel<<<NCTA, TPB>>>(lw, x0, out);
    if (out_size >= 33554432 + 64) tail_kernel<<<1, 64>>>(out);
}

// round 3
// speedup vs baseline: 2.0994x; 2.0994x over previous
#include <cuda_runtime.h>
#include <math.h>

typedef unsigned long long ull;
#define NCTA 128
#define TPB  256

// ---- device scratch (static; allocations forbidden) ----
__device__ float g_u[512u*1024u*64u];   // u[t][d][b]
__device__ float g_s[512u*1024u*64u];   // states[t][d][b]
__device__ float g_x[2][1024*64];       // state ping-pong, layout [k][b]
__device__ int   g_len[64];
__device__ unsigned g_bar_count;
__device__ unsigned g_bar_gen;

// ---- packed f32x2 helpers ----
__device__ __forceinline__ ull pack2(float a, float b){ ull r; asm("mov.b64 %0,{%1,%2};":"=l"(r):"f"(a),"f"(b)); return r; }
__device__ __forceinline__ float2 unpk(ull v){ float2 r; asm("mov.b64 {%0,%1},%2;":"=f"(r.x),"=f"(r.y):"l"(v)); return r; }
__device__ __forceinline__ ull ffma2(ull a, ull b, ull c){ ull d; asm("fma.rn.f32x2 %0,%1,%2,%3;":"=l"(d):"l"(a),"l"(b),"l"(c)); return d; }
__device__ __forceinline__ ull add2(ull a, ull b){ ull d; asm("add.rn.f32x2 %0,%1,%2;":"=l"(d):"l"(a),"l"(b)); return d; }

// ---- init: x0 broadcast into g_x[0] ([k][b]); zero lengths ----
__global__ void init_kernel(const float* __restrict__ x0) {
    int idx = blockIdx.x * 256 + threadIdx.x;      // 65536
    g_x[0][idx] = x0[idx >> 6];
    if (idx < 64) g_len[idx] = 0;
}

// ---- lengths ----
__global__ void len_kernel(const float* __restrict__ emb) {
    int t = blockIdx.x;
    int b = threadIdx.x >> 2, p = threadIdx.x & 3;
    const float* row = emb + ((size_t)t*64 + b)*300;
    float s = 0.f;
    for (int i = p; i < 300; i += 4) s += row[i];
    s += __shfl_xor_sync(0xffffffffu, s, 1);
    s += __shfl_xor_sync(0xffffffffu, s, 2);
    if (p == 0 && s != 0.f) atomicAdd(&g_len[b], 1);
}

// ---- projection: u[t][d][b] = sum_k win[d][k]*emb[t][b][k] + bias[d] ----
__global__ __launch_bounds__(256) void proj_kernel(const float* __restrict__ emb,
                                                   const float* __restrict__ win,
                                                   const float* __restrict__ bias) {
    __align__(16) __shared__ float Es[32][66];
    __align__(16) __shared__ float Ws[32][64];
    const int tid = threadIdx.x;
    const int tx = tid & 15;          // b-group
    const int ty = tid >> 4;          // d-group
    const int t  = blockIdx.y;
    const int d0 = blockIdx.x * 64;
    const int lb = tid >> 2, lq = tid & 3;

    ull acc[4][2];
    #pragma unroll
    for (int i = 0; i < 4; ++i) { acc[i][0] = 0ull; acc[i][1] = 0ull; }

    for (int k0 = 0; k0 < 300; k0 += 32) {
        #pragma unroll
        for (int j = 0; j < 8; ++j) {
            int kk = lq*8 + j, k = k0 + kk;
            Es[kk][lb] = (k < 300) ? emb[((size_t)t*64 + lb)*300 + k] : 0.f;
            Ws[kk][lb] = (k < 300) ? win[((size_t)(d0 + lb))*300 + k] : 0.f;
        }
        __syncthreads();
        #pragma unroll
        for (int kk = 0; kk < 32; ++kk) {
            ull e01 = *(const ull*)&Es[kk][tx*4];
            ull e23 = *(const ull*)&Es[kk][tx*4 + 2];
            #pragma unroll
            for (int dd = 0; dd < 4; ++dd) {
                float w = Ws[kk][ty*4 + dd];
                ull wp = pack2(w, w);
                acc[dd][0] = ffma2(e01, wp, acc[dd][0]);
                acc[dd][1] = ffma2(e23, wp, acc[dd][1]);
            }
        }
        __syncthreads();
    }
    #pragma unroll
    for (int dd = 0; dd < 4; ++dd) {
        int d = d0 + ty*4 + dd;
        float bb = bias[d];
        float2 p0 = unpk(acc[dd][0]), p1 = unpk(acc[dd][1]);
        float4 o = make_float4(p0.x + bb, p0.y + bb, p1.x + bb, p1.y + bb);
        *(float4*)&g_u[((size_t)t*1024 + d)*64 + tx*4] = o;
    }
}

// ---- grid barrier (all NCTA resident) ----
__device__ __forceinline__ void grid_barrier() {
    __syncthreads();
    if (threadIdx.x == 0) {
        __threadfence();
        volatile unsigned* genp = &g_bar_gen;
        unsigned gen = *genp;
        if (atomicAdd(&g_bar_count, 1u) == NCTA - 1u) {
            atomicExch(&g_bar_count, 0u);
            __threadfence();
            *genp = gen + 1u;
        } else {
            while (*genp == gen) { }
            __threadfence();
        }
    }
    __syncthreads();
}

// ---- persistent scan ----
// Per CTA: 8 rows (d = base..base+7). Thread ct: bq = ct&15 (batch quad),
// ks = ct>>4 (k slice of 64). acc[2r+p] = f32x2 over batches (4bq+2p, +1).
// W in smem as duplicated pairs wsm[k*8+r] = (W[base+r][k], W[base+r][k]).
__global__ __launch_bounds__(TPB, 1) void scan_kernel(const float* __restrict__ layer_w,
                                                      const float* __restrict__ init_state) {
    extern __shared__ __align__(16) unsigned char dsm[];
    ull* wsm  = (ull*)dsm;                 // 1024*8 ull = 64 KB
    ull* part = (ull*)(dsm + 65536);       // 256 rows * 17 ull = 34816 B

    const int ct   = threadIdx.x;
    const int bq   = ct & 15;
    const int ks   = ct >> 4;
    const int base = blockIdx.x * 8;

    // fill W (once): coalesced read, scattered 8B dup-writes
    #pragma unroll
    for (int r = 0; r < 8; ++r) {
        const float* wr = layer_w + (size_t)(base + r) * 1024;
        for (int k = ct; k < 1024; k += TPB) {
            float w = wr[k];
            wsm[(size_t)k * 8 + r] = pack2(w, w);
        }
    }

    // reducer role: thread ct -> (r = ct>>5, bp = ct&31), batches b0=2bp, b1=2bp+1
    const int rr = ct >> 5, bp = ct & 31;
    const int dd = base + rr;
    float xo0 = init_state[dd], xo1 = init_state[dd];
    const int len0 = g_len[2*bp], len1 = g_len[2*bp + 1];

    __syncthreads();

    for (int t = 0; t < 512; ++t) {
        const float* xin  = g_x[t & 1];
        float*       xout = g_x[(t & 1) ^ 1];

        // prefetch u pair for reducer role (hidden behind compute)
        ull upre = *(const ull*)&g_u[((size_t)t*1024 + dd)*64 + 2*bp];

        ull acc[16];
        #pragma unroll
        for (int i = 0; i < 16; ++i) acc[i] = 0ull;

        const float* xp = xin + (size_t)(ks * 64) * 64 + bq * 4;
        for (int kk = 0; kk < 64; kk += 8) {
            ulonglong2 xv[8];
            #pragma unroll
            for (int j = 0; j < 8; ++j)
                xv[j] = __ldcg((const ulonglong2*)(xp + (size_t)(kk + j) * 64));
            #pragma unroll
            for (int j = 0; j < 8; ++j) {
                const ull* wk = wsm + (size_t)(ks*64 + kk + j) * 8;
                ulonglong2 wa = *(const ulonglong2*)(wk);
                ulonglong2 wb = *(const ulonglong2*)(wk + 2);
                ulonglong2 wc = *(const ulonglong2*)(wk + 4);
                ulonglong2 wd = *(const ulonglong2*)(wk + 6);
                acc[0]  = ffma2(xv[j].x, wa.x, acc[0]);  acc[1]  = ffma2(xv[j].y, wa.x, acc[1]);
                acc[2]  = ffma2(xv[j].x, wa.y, acc[2]);  acc[3]  = ffma2(xv[j].y, wa.y, acc[3]);
                acc[4]  = ffma2(xv[j].x, wb.x, acc[4]);  acc[5]  = ffma2(xv[j].y, wb.x, acc[5]);
                acc[6]  = ffma2(xv[j].x, wb.y, acc[6]);  acc[7]  = ffma2(xv[j].y, wb.y, acc[7]);
                acc[8]  = ffma2(xv[j].x, wc.x, acc[8]);  acc[9]  = ffma2(xv[j].y, wc.x, acc[9]);
                acc[10] = ffma2(xv[j].x, wc.y, acc[10]); acc[11] = ffma2(xv[j].y, wc.y, acc[11]);
                acc[12] = ffma2(xv[j].x, wd.x, acc[12]); acc[13] = ffma2(xv[j].y, wd.x, acc[13]);
                acc[14] = ffma2(xv[j].x, wd.y, acc[14]); acc[15] = ffma2(xv[j].y, wd.y, acc[15]);
            }
        }

        // write partials: row = ct (= ks*16 + bq), padded stride 17
        ull* prow = part + (size_t)ct * 17;
        #pragma unroll
        for (int i = 0; i < 16; ++i) prow[i] = acc[i];
        __syncthreads();

        // reduce 16 k-slices for output (d = base+rr, batches 2bp, 2bp+1)
        const int bq2 = bp >> 1, pp = bp & 1;
        ull s = upre;
        #pragma unroll
        for (int kss = 0; kss < 16; ++kss)
            s = add2(s, part[(size_t)(kss*16 + bq2)*17 + (rr*2 + pp)]);

        float2 a = unpk(s);
        float n0 = 0.5f * tanhf(a.x) + 0.5f * xo0;
        float n1 = 0.5f * tanhf(a.y) + 0.5f * xo1;
        if (t >= len0) n0 = 0.f;
        if (t >= len1) n1 = 0.f;
        xo0 = n0; xo1 = n1;

        __stcg((float2*)(xout + (size_t)dd*64 + 2*bp), make_float2(n0, n1));
        *(float2*)&g_s[((size_t)t*1024 + dd)*64 + 2*bp] = make_float2(n0, n1);

        grid_barrier();
    }
}

// ---- transpose g_s[t][d][b] -> out[b][t][d] ----
__global__ __launch_bounds__(256) void trans_kernel(float* __restrict__ out) {
    __shared__ float ts[64][65];
    const int t  = blockIdx.y;
    const int d0 = blockIdx.x * 64;
    const int tid = threadIdx.x;
    #pragma unroll
    for (int j = 0; j < 16; ++j) {
        int idx = j*256 + tid;
        int dl = idx >> 6, b = idx & 63;
        ts[dl][b] = g_s[(((size_t)t << 10) + d0 + dl)*64 + b];
    }
    __syncthreads();
    #pragma unroll
    for (int j = 0; j < 16; ++j) {
        int idx = j*256 + tid;
        int b = idx >> 6, dl = idx & 63;
        out[((size_t)b*512 + t)*1024 + d0 + dl] = ts[dl][b];
    }
}

__global__ void tail_kernel(float* out) {
    int b = threadIdx.x;
    if (b < 64) out[33554432u + b] = (float)g_len[b];
}

extern "C" void kernel_launch(void* const* d_in, const int* in_sizes, int n_in,
                              void* d_out, int out_size) {
    const float* emb  = (const float*)d_in[0];
    const float* win  = (const float*)d_in[1];
    const float* lw   = (const float*)d_in[2];
    const float* bias = (const float*)d_in[3];
    const float* x0   = (const float*)d_in[4];
    float* out = (float*)d_out;

    static int smem_set = 0;
    if (!smem_set) {
        cudaFuncSetAttribute(scan_kernel, cudaFuncAttributeMaxDynamicSharedMemorySize, 100352);
        smem_set = 1;
    }

    init_kernel<<<256, 256>>>(x0);
    len_kernel<<<512, 256>>>(emb);
    proj_kernel<<<dim3(16, 512), 256>>>(emb, win, bias);
    scan_kernel<<<NCTA, TPB, 100352>>>(lw, x0);
    trans_kernel<<<dim3(16, 512), 256>>>(out);
    if (out_size >= 33554432 + 64) tail_kernel<<<1, 64>>>(out);
}

// round 5
// speedup vs baseline: 2.2068x; 1.0511x over previous
#include <cuda_runtime.h>
#include <math.h>

typedef unsigned long long ull;
#define NCTA 128
#define TPB  512
#define PSTRIDE 18   // partials row stride in ull (EVEN -> 16B-aligned vector stores)

// ---- device scratch (static; allocations forbidden) ----
__device__ float g_u[512u*1024u*64u];   // u[t][d][b]
__device__ float g_s[512u*1024u*64u];   // states[t][d][b]
__device__ float g_x[2][1024*64];       // state ping-pong, layout [k][b]
__device__ int   g_len[64];
__device__ unsigned g_bar_count;
__device__ unsigned g_bar_gen;

// ---- packed f32x2 helpers ----
__device__ __forceinline__ ull pack2(float a, float b){ ull r; asm("mov.b64 %0,{%1,%2};":"=l"(r):"f"(a),"f"(b)); return r; }
__device__ __forceinline__ float2 unpk(ull v){ float2 r; asm("mov.b64 {%0,%1},%2;":"=f"(r.x),"=f"(r.y):"l"(v)); return r; }
__device__ __forceinline__ ull ffma2(ull a, ull b, ull c){ ull d; asm("fma.rn.f32x2 %0,%1,%2,%3;":"=l"(d):"l"(a),"l"(b),"l"(c)); return d; }
__device__ __forceinline__ ull add2(ull a, ull b){ ull d; asm("add.rn.f32x2 %0,%1,%2;":"=l"(d):"l"(a),"l"(b)); return d; }

// ---- init ----
__global__ void init_kernel(const float* __restrict__ x0) {
    int idx = blockIdx.x * 256 + threadIdx.x;
    g_x[0][idx] = x0[idx >> 6];
    if (idx < 64) g_len[idx] = 0;
}

// ---- lengths ----
__global__ void len_kernel(const float* __restrict__ emb) {
    int t = blockIdx.x;
    int b = threadIdx.x >> 2, p = threadIdx.x & 3;
    const float* row = emb + ((size_t)t*64 + b)*300;
    float s = 0.f;
    for (int i = p; i < 300; i += 4) s += row[i];
    s += __shfl_xor_sync(0xffffffffu, s, 1);
    s += __shfl_xor_sync(0xffffffffu, s, 2);
    if (p == 0 && s != 0.f) atomicAdd(&g_len[b], 1);
}

// ---- projection: u[t][d][b] = sum_k win[d][k]*emb[t][b][k] + bias[d] ----
__global__ __launch_bounds__(256) void proj_kernel(const float* __restrict__ emb,
                                                   const float* __restrict__ win,
                                                   const float* __restrict__ bias) {
    __align__(16) __shared__ float Es[32][66];
    __align__(16) __shared__ ull   Wd[32][64];     // duplicated (w,w) pairs
    const int tid = threadIdx.x;
    const int tx = tid & 15;          // b-group
    const int ty = tid >> 4;          // d-group
    const int t  = blockIdx.y;
    const int d0 = blockIdx.x * 64;
    const int lb = tid >> 2, lq = tid & 3;

    ull acc[4][2];
    #pragma unroll
    for (int i = 0; i < 4; ++i) { acc[i][0] = 0ull; acc[i][1] = 0ull; }

    for (int k0 = 0; k0 < 300; k0 += 32) {
        #pragma unroll
        for (int j = 0; j < 8; ++j) {
            int kk = lq*8 + j, k = k0 + kk;
            Es[kk][lb] = (k < 300) ? emb[((size_t)t*64 + lb)*300 + k] : 0.f;
            float w = (k < 300) ? win[((size_t)(d0 + lb))*300 + k] : 0.f;
            Wd[kk][lb] = pack2(w, w);
        }
        __syncthreads();
        #pragma unroll
        for (int kk = 0; kk < 32; ++kk) {
            ull e01 = *(const ull*)&Es[kk][tx*4];
            ull e23 = *(const ull*)&Es[kk][tx*4 + 2];
            ulonglong2 wA = *(const ulonglong2*)&Wd[kk][ty*4];
            ulonglong2 wB = *(const ulonglong2*)&Wd[kk][ty*4 + 2];
            acc[0][0] = ffma2(e01, wA.x, acc[0][0]); acc[0][1] = ffma2(e23, wA.x, acc[0][1]);
            acc[1][0] = ffma2(e01, wA.y, acc[1][0]); acc[1][1] = ffma2(e23, wA.y, acc[1][1]);
            acc[2][0] = ffma2(e01, wB.x, acc[2][0]); acc[2][1] = ffma2(e23, wB.x, acc[2][1]);
            acc[3][0] = ffma2(e01, wB.y, acc[3][0]); acc[3][1] = ffma2(e23, wB.y, acc[3][1]);
        }
        __syncthreads();
    }
    #pragma unroll
    for (int dd = 0; dd < 4; ++dd) {
        int d = d0 + ty*4 + dd;
        float bb = bias[d];
        float2 p0 = unpk(acc[dd][0]), p1 = unpk(acc[dd][1]);
        float4 o = make_float4(p0.x + bb, p0.y + bb, p1.x + bb, p1.y + bb);
        *(float4*)&g_u[((size_t)t*1024 + d)*64 + tx*4] = o;
    }
}

// ---- grid barrier (all NCTA resident) ----
__device__ __forceinline__ void grid_barrier() {
    __syncthreads();
    if (threadIdx.x == 0) {
        __threadfence();
        volatile unsigned* genp = &g_bar_gen;
        unsigned gen = *genp;
        if (atomicAdd(&g_bar_count, 1u) == NCTA - 1u) {
            atomicExch(&g_bar_count, 0u);
            __threadfence();
            *genp = gen + 1u;
        } else {
            while (*genp == gen) { }
            __threadfence();
        }
    }
    __syncthreads();
}

// ---- persistent scan ----
// 128 CTAs x 512 threads. CTA: rows base..base+7, all 64 batches.
// Thread ct: bq = ct&15 (batch quad), ks = ct>>4 (k slice of 32).
// W smem: ull at widx(k,r) = k*8 + r + (k>>5)*2  (skew breaks half-warp bank clash)
__global__ __launch_bounds__(TPB, 1) void scan_kernel(const float* __restrict__ layer_w,
                                                      const float* __restrict__ init_state) {
    extern __shared__ __align__(16) unsigned char dsm[];
    ull* wsm  = (ull*)dsm;                  // 8256 ull = 66048 B
    ull* part = (ull*)(dsm + 66048);        // 512 rows * PSTRIDE ull = 73728 B

    const int ct   = threadIdx.x;
    const int bq   = ct & 15;
    const int ks   = ct >> 4;               // 0..31
    const int base = blockIdx.x * 8;

    // fill W pairs once
    for (int k = ct; k < 1024; k += TPB) {
        #pragma unroll
        for (int r = 0; r < 8; ++r) {
            float w = layer_w[(size_t)(base + r) * 1024 + k];
            wsm[(size_t)k * 8 + r + (k >> 5) * 2] = pack2(w, w);
        }
    }

    // reducer role (ct < 256): rr = row 0..7, bp = batch pair 0..31
    const int rr = (ct >> 5) & 7, bp = ct & 31;
    const int dd = base + rr;
    float xo0 = init_state[dd], xo1 = init_state[dd];
    int len0 = 0, len1 = 0;
    if (ct < 256) { len0 = g_len[2*bp]; len1 = g_len[2*bp + 1]; }

    const ull* wbase = wsm + (size_t)ks * 258;   // ks*32*8 + ks*2
    __syncthreads();

    for (int t = 0; t < 512; ++t) {
        const float* xin  = g_x[t & 1];
        float*       xout = g_x[(t & 1) ^ 1];

        ull upre = 0ull;
        if (ct < 256) upre = *(const ull*)&g_u[((size_t)t*1024 + dd)*64 + 2*bp];

        ull acc[16];
        #pragma unroll
        for (int i = 0; i < 16; ++i) acc[i] = 0ull;

        const float* xp = xin + (size_t)(ks * 32) * 64 + bq * 4;
        #pragma unroll
        for (int kk = 0; kk < 32; kk += 4) {
            ulonglong2 xv[4];
            #pragma unroll
            for (int j = 0; j < 4; ++j)
                xv[j] = __ldcg((const ulonglong2*)(xp + (size_t)(kk + j) * 64));
            #pragma unroll
            for (int j = 0; j < 4; ++j) {
                const ull* wk = wbase + (size_t)(kk + j) * 8;
                ulonglong2 wa = *(const ulonglong2*)(wk);
                ulonglong2 wb = *(const ulonglong2*)(wk + 2);
                ulonglong2 wc = *(const ulonglong2*)(wk + 4);
                ulonglong2 wd = *(const ulonglong2*)(wk + 6);
                acc[0]  = ffma2(xv[j].x, wa.x, acc[0]);  acc[1]  = ffma2(xv[j].y, wa.x, acc[1]);
                acc[2]  = ffma2(xv[j].x, wa.y, acc[2]);  acc[3]  = ffma2(xv[j].y, wa.y, acc[3]);
                acc[4]  = ffma2(xv[j].x, wb.x, acc[4]);  acc[5]  = ffma2(xv[j].y, wb.x, acc[5]);
                acc[6]  = ffma2(xv[j].x, wb.y, acc[6]);  acc[7]  = ffma2(xv[j].y, wb.y, acc[7]);
                acc[8]  = ffma2(xv[j].x, wc.x, acc[8]);  acc[9]  = ffma2(xv[j].y, wc.x, acc[9]);
                acc[10] = ffma2(xv[j].x, wc.y, acc[10]); acc[11] = ffma2(xv[j].y, wc.y, acc[11]);
                acc[12] = ffma2(xv[j].x, wd.x, acc[12]); acc[13] = ffma2(xv[j].y, wd.x, acc[13]);
                acc[14] = ffma2(xv[j].x, wd.y, acc[14]); acc[15] = ffma2(xv[j].y, wd.y, acc[15]);
            }
        }

        // partials: row ct (= ks*16 + bq), stride PSTRIDE (even -> aligned)
        ull* prow = part + (size_t)ct * PSTRIDE;
        #pragma unroll
        for (int i = 0; i < 8; ++i)
            *(ulonglong2*)&prow[2*i] = make_ulonglong2(acc[2*i], acc[2*i+1]);
        __syncthreads();

        if (ct < 256) {
            const int bq2 = bp >> 1, col = rr*2 + (bp & 1);
            ull s = upre;
            #pragma unroll
            for (int kss = 0; kss < 32; ++kss)
                s = add2(s, part[(size_t)(kss*16 + bq2)*PSTRIDE + col]);

            float2 a = unpk(s);
            float n0 = 0.5f * tanhf(a.x) + 0.5f * xo0;
            float n1 = 0.5f * tanhf(a.y) + 0.5f * xo1;
            if (t >= len0) n0 = 0.f;
            if (t >= len1) n1 = 0.f;
            xo0 = n0; xo1 = n1;

            __stcg((float2*)(xout + (size_t)dd*64 + 2*bp), make_float2(n0, n1));
            *(float2*)&g_s[((size_t)t*1024 + dd)*64 + 2*bp] = make_float2(n0, n1);
        }
        grid_barrier();
    }
}

// ---- transpose g_s[t][d][b] -> out[b][t][d] ----
__global__ __launch_bounds__(256) void trans_kernel(float* __restrict__ out) {
    __shared__ float ts[64][65];
    const int t  = blockIdx.y;
    const int d0 = blockIdx.x * 64;
    const int tid = threadIdx.x;
    #pragma unroll
    for (int j = 0; j < 16; ++j) {
        int idx = j*256 + tid;
        int dl = idx >> 6, b = idx & 63;
        ts[dl][b] = g_s[(((size_t)t << 10) + d0 + dl)*64 + b];
    }
    __syncthreads();
    #pragma unroll
    for (int j = 0; j < 16; ++j) {
        int idx = j*256 + tid;
        int b = idx >> 6, dl = idx & 63;
        out[((size_t)b*512 + t)*1024 + d0 + dl] = ts[dl][b];
    }
}

__global__ void tail_kernel(float* out) {
    int b = threadIdx.x;
    if (b < 64) out[33554432u + b] = (float)g_len[b];
}

extern "C" void kernel_launch(void* const* d_in, const int* in_sizes, int n_in,
                              void* d_out, int out_size) {
    const float* emb  = (const float*)d_in[0];
    const float* win  = (const float*)d_in[1];
    const float* lw   = (const float*)d_in[2];
    const float* bias = (const float*)d_in[3];
    const float* x0   = (const float*)d_in[4];
    float* out = (float*)d_out;

    static int smem_set = 0;
    if (!smem_set) {
        cudaFuncSetAttribute(scan_kernel, cudaFuncAttributeMaxDynamicSharedMemorySize, 139776);
        smem_set = 1;
    }

    init_kernel<<<256, 256>>>(x0);
    len_kernel<<<512, 256>>>(emb);
    proj_kernel<<<dim3(16, 512), 256>>>(emb, win, bias);
    scan_kernel<<<NCTA, TPB, 139776>>>(lw, x0);
    trans_kernel<<<dim3(16, 512), 256>>>(out);
    if (out_size >= 33554432 + 64) tail_kernel<<<1, 64>>>(out);
}

// round 6
// speedup vs baseline: 2.5146x; 1.1395x over previous
#include <cuda_runtime.h>
#include <math.h>

typedef unsigned long long ull;
#define NCTA 128
#define TPB  512
#define PSTRIDE 18   // partials row stride in ull (EVEN -> 16B-aligned vector stores)

// ---- device scratch (static; allocations forbidden) ----
__device__ float g_u[512u*1024u*64u];   // u[t][d][b]
__device__ float g_s[512u*1024u*64u];   // states[t][d][b]
__device__ float g_x[2][1024*64];       // state ping-pong, layout [k][b]
__device__ int   g_len[64];
__device__ unsigned g_bar_count;
__device__ unsigned g_bar_gen;

// ---- packed f32x2 helpers ----
__device__ __forceinline__ ull pack2(float a, float b){ ull r; asm("mov.b64 %0,{%1,%2};":"=l"(r):"f"(a),"f"(b)); return r; }
__device__ __forceinline__ float2 unpk(ull v){ float2 r; asm("mov.b64 {%0,%1},%2;":"=f"(r.x),"=f"(r.y):"l"(v)); return r; }
__device__ __forceinline__ ull ffma2(ull a, ull b, ull c){ ull d; asm("fma.rn.f32x2 %0,%1,%2,%3;":"=l"(d):"l"(a),"l"(b),"l"(c)); return d; }
__device__ __forceinline__ ull add2(ull a, ull b){ ull d; asm("add.rn.f32x2 %0,%1,%2;":"=l"(d):"l"(a),"l"(b)); return d; }

// ---- init ----
__global__ void init_kernel(const float* __restrict__ x0) {
    int idx = blockIdx.x * 256 + threadIdx.x;
    g_x[0][idx] = x0[idx >> 6];
    if (idx < 64) g_len[idx] = 0;
}

// ---- lengths ----
__global__ void len_kernel(const float* __restrict__ emb) {
    int t = blockIdx.x;
    int b = threadIdx.x >> 2, p = threadIdx.x & 3;
    const float* row = emb + ((size_t)t*64 + b)*300;
    float s = 0.f;
    for (int i = p; i < 300; i += 4) s += row[i];
    s += __shfl_xor_sync(0xffffffffu, s, 1);
    s += __shfl_xor_sync(0xffffffffu, s, 2);
    if (p == 0 && s != 0.f) atomicAdd(&g_len[b], 1);
}

// ---- projection: 2 timesteps per block; W tile loaded once per pair ----
__global__ __launch_bounds__(256) void proj_kernel(const float* __restrict__ emb,
                                                   const float* __restrict__ win,
                                                   const float* __restrict__ bias) {
    __align__(16) __shared__ float Es[2][32][66];
    __align__(16) __shared__ ull   Wd[32][64];     // duplicated (w,w) pairs
    const int tid = threadIdx.x;
    const int tx = tid & 15;          // b-group
    const int ty = tid >> 4;          // d-group
    const int t0 = blockIdx.y * 2;
    const int d0 = blockIdx.x * 64;
    const int lb = tid >> 2, lq = tid & 3;

    ull acc[2][4][2];
    #pragma unroll
    for (int h = 0; h < 2; ++h)
        #pragma unroll
        for (int i = 0; i < 4; ++i) { acc[h][i][0] = 0ull; acc[h][i][1] = 0ull; }

    for (int k0 = 0; k0 < 300; k0 += 32) {
        #pragma unroll
        for (int j = 0; j < 8; ++j) {
            int kk = lq*8 + j, k = k0 + kk;
            bool ok = (k < 300);
            Es[0][kk][lb] = ok ? emb[((size_t)t0*64 + lb)*300 + k] : 0.f;
            Es[1][kk][lb] = ok ? emb[((size_t)(t0+1)*64 + lb)*300 + k] : 0.f;
            float w = ok ? win[((size_t)(d0 + lb))*300 + k] : 0.f;
            Wd[kk][lb] = pack2(w, w);
        }
        __syncthreads();
        #pragma unroll
        for (int kk = 0; kk < 32; ++kk) {
            ulonglong2 wA = *(const ulonglong2*)&Wd[kk][ty*4];
            ulonglong2 wB = *(const ulonglong2*)&Wd[kk][ty*4 + 2];
            #pragma unroll
            for (int h = 0; h < 2; ++h) {
                ull e01 = *(const ull*)&Es[h][kk][tx*4];
                ull e23 = *(const ull*)&Es[h][kk][tx*4 + 2];
                acc[h][0][0] = ffma2(e01, wA.x, acc[h][0][0]); acc[h][0][1] = ffma2(e23, wA.x, acc[h][0][1]);
                acc[h][1][0] = ffma2(e01, wA.y, acc[h][1][0]); acc[h][1][1] = ffma2(e23, wA.y, acc[h][1][1]);
                acc[h][2][0] = ffma2(e01, wB.x, acc[h][2][0]); acc[h][2][1] = ffma2(e23, wB.x, acc[h][2][1]);
                acc[h][3][0] = ffma2(e01, wB.y, acc[h][3][0]); acc[h][3][1] = ffma2(e23, wB.y, acc[h][3][1]);
            }
        }
        __syncthreads();
    }
    #pragma unroll
    for (int h = 0; h < 2; ++h)
        #pragma unroll
        for (int dd = 0; dd < 4; ++dd) {
            int d = d0 + ty*4 + dd;
            float bb = bias[d];
            float2 p0 = unpk(acc[h][dd][0]), p1 = unpk(acc[h][dd][1]);
            float4 o = make_float4(p0.x + bb, p0.y + bb, p1.x + bb, p1.y + bb);
            *(float4*)&g_u[((size_t)(t0+h)*1024 + d)*64 + tx*4] = o;
        }
}

// ---- grid barrier: acq_rel arrive + acquire poll (no full fences) ----
__device__ __forceinline__ void grid_barrier() {
    __syncthreads();
    if (threadIdx.x == 0) {
        unsigned gen;
        asm volatile("ld.acquire.gpu.global.u32 %0, [%1];" : "=r"(gen) : "l"(&g_bar_gen));
        unsigned prev;
        asm volatile("atom.acq_rel.gpu.global.add.u32 %0, [%1], 1;" : "=r"(prev) : "l"(&g_bar_count));
        if (prev == NCTA - 1u) {
            asm volatile("st.relaxed.gpu.global.u32 [%0], %1;" :: "l"(&g_bar_count), "r"(0u));
            asm volatile("st.release.gpu.global.u32 [%0], %1;" :: "l"(&g_bar_gen), "r"(gen + 1u));
        } else {
            unsigned g2;
            do {
                asm volatile("ld.acquire.gpu.global.u32 %0, [%1];" : "=r"(g2) : "l"(&g_bar_gen));
            } while (g2 == gen);
        }
    }
    __syncthreads();
}

// ---- persistent scan (pipelined x loads) ----
__global__ __launch_bounds__(TPB, 1) void scan_kernel(const float* __restrict__ layer_w,
                                                      const float* __restrict__ init_state) {
    extern __shared__ __align__(16) unsigned char dsm[];
    ull* wsm  = (ull*)dsm;                  // 8256 ull = 66048 B
    ull* part = (ull*)(dsm + 66048);        // 512 * PSTRIDE ull = 73728 B

    const int ct   = threadIdx.x;
    const int bq   = ct & 15;
    const int ks   = ct >> 4;               // 0..31
    const int base = blockIdx.x * 8;

    for (int k = ct; k < 1024; k += TPB) {
        #pragma unroll
        for (int r = 0; r < 8; ++r) {
            float w = layer_w[(size_t)(base + r) * 1024 + k];
            wsm[(size_t)k * 8 + r + (k >> 5) * 2] = pack2(w, w);
        }
    }

    const int rr = (ct >> 5) & 7, bp = ct & 31;
    const int dd = base + rr;
    float xo0 = init_state[dd], xo1 = init_state[dd];
    int len0 = 0, len1 = 0;
    if (ct < 256) { len0 = g_len[2*bp]; len1 = g_len[2*bp + 1]; }

    const ull* wbase = wsm + (size_t)ks * 258;   // ks*32*8 + ks*2
    __syncthreads();

    for (int t = 0; t < 512; ++t) {
        const float* xin  = g_x[t & 1];
        float*       xout = g_x[(t & 1) ^ 1];

        ull upre = 0ull;
        if (ct < 256) upre = *(const ull*)&g_u[((size_t)t*1024 + dd)*64 + 2*bp];

        ull acc[16];
        #pragma unroll
        for (int i = 0; i < 16; ++i) acc[i] = 0ull;

        const float* xp = xin + (size_t)(ks * 32) * 64 + bq * 4;

        // 2-stage register double-buffer over 8 chunks of 4 k
        ulonglong2 xva[4], xvb[4];
        #pragma unroll
        for (int j = 0; j < 4; ++j)
            xva[j] = __ldcg((const ulonglong2*)(xp + (size_t)j * 64));

        #pragma unroll
        for (int c = 0; c < 8; ++c) {
            ulonglong2* cur = (c & 1) ? xvb : xva;
            ulonglong2* nxt = (c & 1) ? xva : xvb;
            if (c < 7) {
                #pragma unroll
                for (int j = 0; j < 4; ++j)
                    nxt[j] = __ldcg((const ulonglong2*)(xp + (size_t)((c + 1) * 4 + j) * 64));
            }
            #pragma unroll
            for (int j = 0; j < 4; ++j) {
                const ull* wk = wbase + (size_t)(c * 4 + j) * 8;
                ulonglong2 wa = *(const ulonglong2*)(wk);
                ulonglong2 wb = *(const ulonglong2*)(wk + 2);
                ulonglong2 wc = *(const ulonglong2*)(wk + 4);
                ulonglong2 wd = *(const ulonglong2*)(wk + 6);
                acc[0]  = ffma2(cur[j].x, wa.x, acc[0]);  acc[1]  = ffma2(cur[j].y, wa.x, acc[1]);
                acc[2]  = ffma2(cur[j].x, wa.y, acc[2]);  acc[3]  = ffma2(cur[j].y, wa.y, acc[3]);
                acc[4]  = ffma2(cur[j].x, wb.x, acc[4]);  acc[5]  = ffma2(cur[j].y, wb.x, acc[5]);
                acc[6]  = ffma2(cur[j].x, wb.y, acc[6]);  acc[7]  = ffma2(cur[j].y, wb.y, acc[7]);
                acc[8]  = ffma2(cur[j].x, wc.x, acc[8]);  acc[9]  = ffma2(cur[j].y, wc.x, acc[9]);
                acc[10] = ffma2(cur[j].x, wc.y, acc[10]); acc[11] = ffma2(cur[j].y, wc.y, acc[11]);
                acc[12] = ffma2(cur[j].x, wd.x, acc[12]); acc[13] = ffma2(cur[j].y, wd.x, acc[13]);
                acc[14] = ffma2(cur[j].x, wd.y, acc[14]); acc[15] = ffma2(cur[j].y, wd.y, acc[15]);
            }
        }

        ull* prow = part + (size_t)ct * PSTRIDE;
        #pragma unroll
        for (int i = 0; i < 8; ++i)
            *(ulonglong2*)&prow[2*i] = make_ulonglong2(acc[2*i], acc[2*i+1]);
        __syncthreads();

        if (ct < 256) {
            const int bq2 = bp >> 1, col = rr*2 + (bp & 1);
            ull s0 = upre, s1 = 0ull, s2 = 0ull, s3 = 0ull;
            #pragma unroll
            for (int kss = 0; kss < 32; kss += 4) {
                s0 = add2(s0, part[(size_t)((kss+0)*16 + bq2)*PSTRIDE + col]);
                s1 = add2(s1, part[(size_t)((kss+1)*16 + bq2)*PSTRIDE + col]);
                s2 = add2(s2, part[(size_t)((kss+2)*16 + bq2)*PSTRIDE + col]);
                s3 = add2(s3, part[(size_t)((kss+3)*16 + bq2)*PSTRIDE + col]);
            }
            ull s = add2(add2(s0, s1), add2(s2, s3));

            float2 a = unpk(s);
            float n0 = 0.5f * tanhf(a.x) + 0.5f * xo0;
            float n1 = 0.5f * tanhf(a.y) + 0.5f * xo1;
            if (t >= len0) n0 = 0.f;
            if (t >= len1) n1 = 0.f;
            xo0 = n0; xo1 = n1;

            __stcg((float2*)(xout + (size_t)dd*64 + 2*bp), make_float2(n0, n1));
            *(float2*)&g_s[((size_t)t*1024 + dd)*64 + 2*bp] = make_float2(n0, n1);
        }
        grid_barrier();
    }
}

// ---- transpose g_s[t][d][b] -> out[b][t][d] ----
__global__ __launch_bounds__(256) void trans_kernel(float* __restrict__ out) {
    __shared__ float ts[64][65];
    const int t  = blockIdx.y;
    const int d0 = blockIdx.x * 64;
    const int tid = threadIdx.x;
    #pragma unroll
    for (int j = 0; j < 16; ++j) {
        int idx = j*256 + tid;
        int dl = idx >> 6, b = idx & 63;
        ts[dl][b] = g_s[(((size_t)t << 10) + d0 + dl)*64 + b];
    }
    __syncthreads();
    #pragma unroll
    for (int j = 0; j < 16; ++j) {
        int idx = j*256 + tid;
        int b = idx >> 6, dl = idx & 63;
        out[((size_t)b*512 + t)*1024 + d0 + dl] = ts[dl][b];
    }
}

__global__ void tail_kernel(float* out) {
    int b = threadIdx.x;
    if (b < 64) out[33554432u + b] = (float)g_len[b];
}

extern "C" void kernel_launch(void* const* d_in, const int* in_sizes, int n_in,
                              void* d_out, int out_size) {
    const float* emb  = (const float*)d_in[0];
    const float* win  = (const float*)d_in[1];
    const float* lw   = (const float*)d_in[2];
    const float* bias = (const float*)d_in[3];
    const float* x0   = (const float*)d_in[4];
    float* out = (float*)d_out;

    static int smem_set = 0;
    if (!smem_set) {
        cudaFuncSetAttribute(scan_kernel, cudaFuncAttributeMaxDynamicSharedMemorySize, 139776);
        smem_set = 1;
    }

    init_kernel<<<256, 256>>>(x0);
    len_kernel<<<512, 256>>>(emb);
    proj_kernel<<<dim3(16, 256), 256>>>(emb, win, bias);
    scan_kernel<<<NCTA, TPB, 139776>>>(lw, x0);
    trans_kernel<<<dim3(16, 512), 256>>>(out);
    if (out_size >= 33554432 + 64) tail_kernel<<<1, 64>>>(out);
}